// round 17
// baseline (speedup 1.0000x reference)
#include <cuda_runtime.h>
#include <cstdint>

// ---------------------------------------------------------------------------
// out = resize(patch_mean(conv3x3(x,gw,gb) + conv1x1(x,tw,tb), 7), HxW)
// Linear algebra: feat never materialized; 81 border/total stats per (b,ci)
// plane -> 49 patch means -> factored bilinear. Three lean serial launches:
//   k1: one-pass read of x (2 rows/warp) -> stats/partials   (BW-bound)
//   kmid: partials -> 49 means only (g_rows table eliminated)
//   k3: stages the 49 means in smem, computes its own two col-interpolated
//       float4s per thread (hidden under the store stream), 8 STG.128.
// ---------------------------------------------------------------------------

#define H 512
#define W 512
#define B_SZ 32
#define CIN 4
#define COUT 2
#define NPLANES (B_SZ * CIN)        // 128
#define NQ (B_SZ * COUT)            // 64
#define STATS_PER_PLANE 81          // [0]=T, [1..8]=rowsum(0..3,508..511),
                                    // [9..16]=colsum(0..3,508..511),
                                    // [17..80]=corner[r8][c8]
#define ROWS_PER_BLOCK 16
#define BLOCKS_PER_PLANE 32         // 16 rows per block
#define PART_PER_BLOCK 9            // T, colL[4], colR[4]

__device__ float g_stats[NPLANES * STATS_PER_PLANE];
__device__ float g_part[NPLANES * BLOCKS_PER_PLANE * PART_PER_BLOCK];
__device__ float g_m[NQ * 49];      // 49 patch means per q

// ---------------------------------------------------------------------------
// k1: per-plane reductions over x. grid (32, 128), block 256, 2 rows/warp.
// x read exactly once, fully coalesced. Unique-writer stores -> deterministic.
// ---------------------------------------------------------------------------
__global__ void __launch_bounds__(256) k1_reduce(const float* __restrict__ x) {
    const int plane = blockIdx.y;
    const int rb    = blockIdx.x;
    const int warp  = threadIdx.x >> 5;
    const int lane  = threadIdx.x & 31;
    const int row0  = rb * ROWS_PER_BLOCK + warp * 2;

    const float4* r0 = reinterpret_cast<const float4*>(
        x + ((size_t)plane << 18) + (size_t)row0 * W);
    const float4* r1 = r0 + (W / 4);

    float4 a0 = __ldcs(r0 + lane);
    float4 a1 = __ldcs(r0 + lane + 32);
    float4 a2 = __ldcs(r0 + lane + 64);
    float4 a3 = __ldcs(r0 + lane + 96);
    float4 b0 = __ldcs(r1 + lane);
    float4 b1 = __ldcs(r1 + lane + 32);
    float4 b2 = __ldcs(r1 + lane + 64);
    float4 b3 = __ldcs(r1 + lane + 96);

    float s0 = (a0.x + a0.y) + (a0.z + a0.w)
             + (a1.x + a1.y) + (a1.z + a1.w)
             + (a2.x + a2.y) + (a2.z + a2.w)
             + (a3.x + a3.y) + (a3.z + a3.w);
    float s1 = (b0.x + b0.y) + (b0.z + b0.w)
             + (b1.x + b1.y) + (b1.z + b1.w)
             + (b2.x + b2.y) + (b2.z + b2.w)
             + (b3.x + b3.y) + (b3.z + b3.w);
    #pragma unroll
    for (int o = 16; o > 0; o >>= 1) {
        s0 += __shfl_down_sync(0xFFFFFFFFu, s0, o);
        s1 += __shfl_down_sync(0xFFFFFFFFu, s1, o);
    }

    __shared__ float sT[8];
    __shared__ float sColL[8][4];
    __shared__ float sColR[8][4];

    float* st = &g_stats[plane * STATS_PER_PLANE];

    auto ridx_of = [] (int row) -> int {
        if (row < 4) return row;
        if (row >= 508) return row - 504;   // 508..511 -> 4..7
        return -1;
    };
    const int ri0 = ridx_of(row0);
    const int ri1 = ridx_of(row0 + 1);

    if (lane == 0) {
        sT[warp] = s0 + s1;
        sColL[warp][0] = a0.x + b0.x; sColL[warp][1] = a0.y + b0.y;
        sColL[warp][2] = a0.z + b0.z; sColL[warp][3] = a0.w + b0.w;
        if (ri0 >= 0) {
            st[1 + ri0] = s0;
            st[17 + ri0 * 8 + 0] = a0.x; st[17 + ri0 * 8 + 1] = a0.y;
            st[17 + ri0 * 8 + 2] = a0.z; st[17 + ri0 * 8 + 3] = a0.w;
        }
        if (ri1 >= 0) {
            st[1 + ri1] = s1;
            st[17 + ri1 * 8 + 0] = b0.x; st[17 + ri1 * 8 + 1] = b0.y;
            st[17 + ri1 * 8 + 2] = b0.z; st[17 + ri1 * 8 + 3] = b0.w;
        }
    }
    if (lane == 31) {
        sColR[warp][0] = a3.x + b3.x; sColR[warp][1] = a3.y + b3.y;
        sColR[warp][2] = a3.z + b3.z; sColR[warp][3] = a3.w + b3.w;
        if (ri0 >= 0) {
            st[17 + ri0 * 8 + 4] = a3.x; st[17 + ri0 * 8 + 5] = a3.y;
            st[17 + ri0 * 8 + 6] = a3.z; st[17 + ri0 * 8 + 7] = a3.w;
        }
        if (ri1 >= 0) {
            st[17 + ri1 * 8 + 4] = b3.x; st[17 + ri1 * 8 + 5] = b3.y;
            st[17 + ri1 * 8 + 6] = b3.z; st[17 + ri1 * 8 + 7] = b3.w;
        }
    }
    __syncthreads();

    if (threadIdx.x == 0) {
        float T = 0.f;
        float cl[4] = {0.f, 0.f, 0.f, 0.f};
        float cr[4] = {0.f, 0.f, 0.f, 0.f};
        #pragma unroll
        for (int w = 0; w < 8; w++) {
            T += sT[w];
            #pragma unroll
            for (int c = 0; c < 4; c++) { cl[c] += sColL[w][c]; cr[c] += sColR[w][c]; }
        }
        float* pp = &g_part[(plane * BLOCKS_PER_PLANE + rb) * PART_PER_BLOCK];
        pp[0] = T;
        #pragma unroll
        for (int c = 0; c < 4; c++) { pp[1 + c] = cl[c]; pp[5 + c] = cr[c]; }
    }
}

// ---------------------------------------------------------------------------
// kmid: partial-reduce + 49 means ONLY (no row table). grid 64, block 256.
// ---------------------------------------------------------------------------
__global__ void __launch_bounds__(256) kmid(const float* __restrict__ gw,
                                            const float* __restrict__ gb,
                                            const float* __restrict__ tw,
                                            const float* __restrict__ tb) {
    const int q  = blockIdx.x;
    const int b  = q >> 1;
    const int co = q & 1;
    const int tid  = threadIdx.x;
    const int warp = tid >> 5;
    const int lane = tid & 31;

    __shared__ float st[CIN][STATS_PER_PLANE];
    __shared__ float rowPre[CIN][5], rowSuf[CIN][5];
    __shared__ float colPre[CIN][5], colSuf[CIN][5];
    __shared__ float cTL[CIN][5][5], cTR[CIN][5][5], cBL[CIN][5][5], cBR[CIN][5][5];
    __shared__ float wc[CIN][9];
    __shared__ float biasS;

    for (int i = tid; i < CIN * STATS_PER_PLANE; i += 256)
        st[i / STATS_PER_PLANE][i % STATS_PER_PLANE] =
            g_stats[(size_t)(b * CIN) * STATS_PER_PLANE + i];

    // warp-shuffle reduce of 32 block-partials: 36 tasks (ci, k) over 8 warps
    for (int task = warp; task < CIN * PART_PER_BLOCK; task += 8) {
        const int ci = task / PART_PER_BLOCK;
        const int k  = task % PART_PER_BLOCK;
        const float* pb = &g_part[(size_t)(b * CIN + ci) * BLOCKS_PER_PLANE * PART_PER_BLOCK + k];
        float v = pb[(size_t)lane * PART_PER_BLOCK];
        #pragma unroll
        for (int o = 16; o > 0; o >>= 1)
            v += __shfl_down_sync(0xFFFFFFFFu, v, o);
        if (lane == 0) {
            if (k == 0)      st[ci][0] = v;
            else if (k < 5)  st[ci][9 + (k - 1)] = v;
            else             st[ci][13 + (k - 5)] = v;
        }
    }
    __syncthreads();

    if (tid < CIN * 4) {
        const int c = tid >> 2, which = tid & 3;
        const int base = (which < 2) ? 1 : 9;
        const bool suf = (which & 1);
        float* dst = (which == 0) ? rowPre[c] : (which == 1) ? rowSuf[c]
                   : (which == 2) ? colPre[c] : colSuf[c];
        float a0 = 0.f;
        float a1 = a0 + st[c][base + (suf ? 7 : 0)];
        float a2 = a1 + st[c][base + (suf ? 6 : 1)];
        float a3 = a2 + st[c][base + (suf ? 5 : 2)];
        float a4 = a3 + st[c][base + (suf ? 4 : 3)];
        dst[0] = a0; dst[1] = a1; dst[2] = a2; dst[3] = a3; dst[4] = a4;
    }
    if (tid >= 32 && tid < 32 + CIN * 25) {
        const int u = tid - 32;
        const int c = u / 25, rem = u % 25;
        const int a = rem / 5, bb = rem % 5;
        float tl = 0.f, tr = 0.f, bl = 0.f, br = 0.f;
        for (int r = 0; r < a; r++)
            for (int cc = 0; cc < bb; cc++) {
                tl += st[c][17 + r * 8 + cc];
                tr += st[c][17 + r * 8 + (7 - cc)];
                bl += st[c][17 + (7 - r) * 8 + cc];
                br += st[c][17 + (7 - r) * 8 + (7 - cc)];
            }
        cTL[c][a][bb] = tl; cTR[c][a][bb] = tr;
        cBL[c][a][bb] = bl; cBR[c][a][bb] = br;
    }
    if (tid >= 160 && tid < 160 + CIN * 9) {
        const int u = tid - 160;
        const int c = u / 9, tap = u % 9;
        float w = gw[(co * CIN + c) * 9 + tap];
        if (tap == 4) w += tw[co * CIN + c];    // fold 1x1 into center tap
        wc[c][tap] = w;
    }
    if (tid == 255) biasS = gb[co] + tb[co];
    __syncthreads();

    if (tid < 49) {
        const int i = tid / 7, j = tid % 7;
        const int r0 = max(0, i - 3), r1 = 509 + min(i, 3);
        const int c0 = max(0, j - 3), c1 = 509 + min(j, 3);
        float acc = biasS * (float)((r1 - r0) * (c1 - c0));
        #pragma unroll
        for (int c = 0; c < CIN; c++) {
            #pragma unroll
            for (int di = 0; di < 3; di++) {
                const int rr0 = max(0, r0 + di - 1);
                const int rr1 = min(H, r1 + di - 1);
                const int nB  = H - rr1;
                #pragma unroll
                for (int dj = 0; dj < 3; dj++) {
                    const int cc0 = max(0, c0 + dj - 1);
                    const int cc1 = min(W, c1 + dj - 1);
                    const int nR  = W - cc1;
                    float rect = st[c][0]
                               - rowPre[c][rr0] - rowSuf[c][nB]
                               - colPre[c][cc0] - colSuf[c][nR]
                               + cTL[c][rr0][cc0] + cTR[c][rr0][nR]
                               + cBL[c][nB][cc0]  + cBR[c][nB][nR];
                    acc += wc[c][di * 3 + dj] * rect;
                }
            }
        }
        g_m[q * 49 + tid] = acc * (1.0f / (float)(H * W));
    }
}

// ---------------------------------------------------------------------------
// k3: row-lerp upsample from the 49 means. grid (32, 64), block 256.
// Stage 49 means in smem; each thread computes its two col-interpolated
// float4s once (LDS + FLOPs hidden under the store stream), then the
// hoisted 8x (4 FFMA + STG.128) loop. Source-row pair changes at most once
// per 16-row window (rare per-row path).
// ---------------------------------------------------------------------------
__global__ void __launch_bounds__(256) k3_upsample(float* __restrict__ out) {
    const int q     = blockIdx.y;
    const int hbase = blockIdx.x * 16;
    const int w4    = threadIdx.x & 127;
    const int rsel  = threadIdx.x >> 7;          // warp-uniform

    __shared__ float sm_m[49];
    if (threadIdx.x < 49) sm_m[threadIdx.x] = g_m[q * 49 + threadIdx.x];
    __syncthreads();

    const float S  = 7.0f / 512.0f;
    const float C  = 0.5f * S - 0.5f;

    const int h0 = hbase + rsel;
    const int hL = h0 + 14;

    float hs0 = (float)h0 * S + C;
    float f0  = floorf(hs0);
    int   i0  = (int)f0;
    int   iL  = (int)floorf((float)hL * S + C);

    // per-column horizontal weights (same for every source row)
    int   cw0[4], cw1[4];
    float cfw[4];
    #pragma unroll
    for (int c = 0; c < 4; c++) {
        const int col = w4 * 4 + c;
        float ws  = ((float)col + 0.5f) * S - 0.5f;
        float iwf = floorf(ws);
        cfw[c] = ws - iwf;
        int iw = (int)iwf;
        cw0[c] = max(iw, 0);
        cw1[c] = min(iw + 1, 6);
    }

    auto col_interp = [&] (int srcRow) -> float4 {
        const float* r = &sm_m[srcRow * 7];
        float4 v;
        float* vp = &v.x;
        #pragma unroll
        for (int c = 0; c < 4; c++) {
            float lo = r[cw0[c]];
            vp[c] = fmaf(cfw[c], r[cw1[c]] - lo, lo);
        }
        return v;
    };

    float4* out4 = reinterpret_cast<float4*>(out)
                 + ((size_t)q << 16) + (size_t)h0 * 128 + w4;

    if (i0 == iL) {
        float4 a = col_interp(max(i0, 0));
        float4 b = col_interp(min(i0 + 1, 6));
        float4 d;
        d.x = b.x - a.x; d.y = b.y - a.y; d.z = b.z - a.z; d.w = b.w - a.w;
        float fh = hs0 - f0;
        #pragma unroll
        for (int k = 0; k < 8; k++) {
            float4 o;
            o.x = fmaf(fh, d.x, a.x);
            o.y = fmaf(fh, d.y, a.y);
            o.z = fmaf(fh, d.z, a.z);
            o.w = fmaf(fh, d.w, a.w);
            out4[k * 256] = o;              // stride 2 rows * 128 f4
            fh += 2.0f * S;
        }
    } else {
        // one boundary in the window: rows i0(clamped), i0+1, i0+2(clamped)
        float4 rlo = col_interp(max(i0, 0));
        float4 rmd = col_interp(i0 + 1);
        float4 rhi = col_interp(min(i0 + 2, 6));
        #pragma unroll
        for (int k = 0; k < 8; k++) {
            const int h = h0 + 2 * k;
            float hs  = (float)h * S + C;
            float ihf = floorf(hs);
            float fh  = hs - ihf;
            bool hiseg = ((int)ihf != i0);
            float4 a = hiseg ? rmd : rlo;
            float4 b = hiseg ? rhi : rmd;
            float4 o;
            o.x = fmaf(fh, b.x - a.x, a.x);
            o.y = fmaf(fh, b.y - a.y, a.y);
            o.z = fmaf(fh, b.z - a.z, a.z);
            o.w = fmaf(fh, b.w - a.w, a.w);
            out4[k * 256] = o;
        }
    }
}

// ---------------------------------------------------------------------------
extern "C" void kernel_launch(void* const* d_in, const int* in_sizes, int n_in,
                              void* d_out, int out_size) {
    const float* x  = (const float*)d_in[0];   // [32,4,512,512]
    const float* gw = (const float*)d_in[1];   // [2,4,3,3]
    const float* gb = (const float*)d_in[2];   // [2]
    const float* tw = (const float*)d_in[3];   // [2,4,1,1]
    const float* tb = (const float*)d_in[4];   // [2]
    float* out = (float*)d_out;                // [32,2,512,512]

    k1_reduce<<<dim3(BLOCKS_PER_PLANE, NPLANES), 256>>>(x);
    kmid<<<NQ, 256>>>(gw, gb, tw, tb);
    k3_upsample<<<dim3(32, NQ), 256>>>(out);
}